// round 12
// baseline (speedup 1.0000x reference)
#include <cuda_runtime.h>
#include <cuda_fp16.h>
#include <math.h>
#include <cstdint>

// ===========================================================================
// Problem constants
// ===========================================================================
#define Bc   16
#define Tc   16
#define Hc   161
#define Wc   181
#define HWc  (Hc*Wc)            // 29141
#define Fc   21
#define F4c  84

// Tile: M = 384 pixels (96 wide x 4 high), N = 88, K = 240 (fp16x3 passes)
// 24 warps: warp = m32 x n44 (4my x 3mx x 2nhalf)
#define TILE_W 96
#define TILE_H 4
#define NTX 2
#define NTY 41
#define NTILES (NTX*NTY*Bc)     // 1312
#define GRID 148

// B matrix: n-major [88][248] fp16 per precision (row 496 B, k pad zero)
#define BROW   248
#define BPLANE_B (88*BROW*2)        // 43,648
#define B_TOTAL_B (2*BPLANE_B)      // 87,296

// Halo: channel-last [prec][6 rows][98 cols][24 ch] fp16
#define HROWS 6
#define HCOLS 98
#define HCH   24
#define HPLANE_B (HROWS*HCOLS*HCH*2)   // 28,224
#define BUF_B (2*HPLANE_B)             // 56,448 per halo buffer

// SMEM layout
#define SM_B     0
#define SM_BIAS  B_TOTAL_B                      // 87,296
#define SM_HALO0 (SM_BIAS + 352)                // 87,648 (16B aligned)
#define SM_HALO1 (SM_HALO0 + BUF_B)             // 144,096
#define SMEM_BYTES (SM_HALO1 + BUF_B + 32)      // 200,576

#define NTHR 768

// Combined input arrays: [b][HW][24] ch-last; ch 0..20 = h, ch 21..23 = x(t)
#define ASZ (Bc*HWc*24)
#define CSZ (Bc*Fc*HWc)
#define XSZ (Bc*Tc*3*HWc)

// ===========================================================================
// Device globals
// ===========================================================================
__device__ __half g_B[2*88*BROW];
__device__ __align__(16) __half g_A0h[ASZ], g_A0l[ASZ];  // read at even t
__device__ __align__(16) __half g_A1h[ASZ], g_A1l[ASZ];  // read at odd t
__device__ float g_c[CSZ];
__device__ __half g_xh[XSZ], g_xl[XSZ];   // planar x hi/lo

// ===========================================================================
// PTX helpers (compute_103-safe)
// ===========================================================================
__device__ __forceinline__ uint32_t smem_to_u32(const void* p) {
    uint32_t a;
    asm("{ .reg .u64 t; cvta.to.shared.u64 t, %1; cvt.u32.u64 %0, t; }"
        : "=r"(a) : "l"(p));
    return a;
}
#define LDSM_X4(r0,r1,r2,r3,addr) \
    asm volatile("ldmatrix.sync.aligned.m8n8.x4.shared.b16 {%0,%1,%2,%3}, [%4];" \
        : "=r"(r0),"=r"(r1),"=r"(r2),"=r"(r3) : "r"(addr))
#define LDSM_X2(r0,r1,addr) \
    asm volatile("ldmatrix.sync.aligned.m8n8.x2.shared.b16 {%0,%1}, [%2];" \
        : "=r"(r0),"=r"(r1) : "r"(addr))
// fp16 inputs, f32 accumulators (main pass)
#define MMA_F32(d,a0,a1,a2,a3,b0,b1) \
    asm volatile("mma.sync.aligned.m16n8k16.row.col.f32.f16.f16.f32 " \
        "{%0,%1,%2,%3}, {%4,%5,%6,%7}, {%8,%9}, {%0,%1,%2,%3};" \
        : "+f"((d)[0]),"+f"((d)[1]),"+f"((d)[2]),"+f"((d)[3]) \
        : "r"(a0),"r"(a1),"r"(a2),"r"(a3),"r"(b0),"r"(b1))
// fp16 inputs, f16 accumulators (correction passes; 2x rate if consumer-style)
#define MMA_F16(e,a0,a1,a2,a3,b0,b1) \
    asm volatile("mma.sync.aligned.m16n8k16.row.col.f16.f16.f16.f16 " \
        "{%0,%1}, {%2,%3,%4,%5}, {%6,%7}, {%0,%1};" \
        : "+r"((e)[0]),"+r"((e)[1]) \
        : "r"(a0),"r"(a1),"r"(a2),"r"(a3),"r"(b0),"r"(b1))
#define CP_ASYNC16(dst, src, sz) \
    asm volatile("cp.async.ca.shared.global [%0], [%1], 16, %2;" \
        :: "r"(dst), "l"(src), "r"(sz) : "memory")
#define CP_COMMIT() asm volatile("cp.async.commit_group;" ::: "memory")
#define CP_WAIT0()  asm volatile("cp.async.wait_group 0;" ::: "memory")

__device__ __forceinline__ float hsig(float v) {
    return fminf(fmaxf(0.2f*v + 0.5f, 0.0f), 1.0f);
}

// ===========================================================================
// Aux kernels
// ===========================================================================
__global__ void init_kernel(const float* __restrict__ x) {
    for (int i = blockIdx.x*blockDim.x + threadIdx.x; i < ASZ; i += gridDim.x*blockDim.x) {
        int ch = i % 24;
        int p  = (i / 24) % HWc;
        int b  = i / (24*HWc);
        __half vh = __float2half_rn(0.0f), vl = vh;
        if (ch >= 21) {
            float v = x[(((size_t)(b*Tc)*HWc) + p)*3 + (ch - 21)];
            vh = __float2half_rn(v);
            vl = __float2half_rn(v - __half2float(vh));
        }
        g_A0h[i] = vh;
        g_A0l[i] = vl;
    }
    for (int i = blockIdx.x*blockDim.x + threadIdx.x; i < CSZ; i += gridDim.x*blockDim.x)
        g_c[i] = 0.0f;
}

__global__ void xsplit_kernel(const float* __restrict__ x) {
    for (int i = blockIdx.x*blockDim.x + threadIdx.x; i < XSZ; i += gridDim.x*blockDim.x) {
        int p  = i % HWc;
        int r  = i / HWc;
        int c  = r % 3;
        int bt = r / 3;
        float v = x[((size_t)bt*HWc + p)*3 + c];
        __half hi = __float2half_rn(v);
        g_xh[i] = hi;
        g_xl[i] = __float2half_rn(v - __half2float(hi));
    }
}

// Pack weights: B[prec][n][k], n = 4*co+g, k = dy*80 + dx*24 + cin
// cin: 0..20 = h (rkern), 21..23 = x (kern); k%80>=72 and k>=240 zero pad
__global__ void packB_kernel(const float* __restrict__ kern, const float* __restrict__ rkern) {
    int i = blockIdx.x*blockDim.x + threadIdx.x;
    const int TOT = 2*88*BROW;
    if (i >= TOT) return;
    int prec = i / (88*BROW);
    int r    = i - prec*(88*BROW);
    int n    = r / BROW;
    int k    = r - n*BROW;
    int co = n >> 2, g = n & 3;
    float w = 0.0f;
    if (k < 240 && co < Fc) {
        int dy = k / 80, r2 = k - dy*80;
        if (r2 < 72) {
            int dx = r2 / 24, cin = r2 - dx*24;
            int col = g*Fc + co;
            if (cin < 21) w = rkern[((dy*3 + dx)*Fc + cin     )*F4c + col];
            else          w = kern [((dy*3 + dx)*3  + (cin-21))*F4c + col];
        }
    }
    __half hi = __float2half_rn(w);
    g_B[i] = prec ? __float2half_rn(w - __half2float(hi)) : hi;
}

// ===========================================================================
// Persistent step kernel: 24 warps (m32n44), fp16x3 HMMA, f16-acc corrections
// ===========================================================================
__device__ __forceinline__ void prefetch_halo(
    uint32_t dstbase, int b, int x0, int y0,
    const __half* __restrict__ Ah, const __half* __restrict__ Al,
    int tid) {
    const int TOTE = 2*HROWS*HCOLS;     // 1176 pixel-entries
    for (int i = tid; i < TOTE; i += NTHR) {
        int c = i % HCOLS;
        int r = (i / HCOLS) % HROWS;
        int p = i / (HCOLS*HROWS);
        int gy = y0 + r - 1, gx = x0 + c - 1;
        bool ok = ((unsigned)gy < (unsigned)Hc) && ((unsigned)gx < (unsigned)Wc);
        size_t off = ok ? ((size_t)b*HWc + (size_t)gy*Wc + gx)*24 : 0;
        const __half* src = (p ? Al : Ah) + off;
        uint32_t dst = dstbase + (uint32_t)p*HPLANE_B + (uint32_t)(r*HCOLS + c)*48;
        uint32_t sz = ok ? 16u : 0u;
        #pragma unroll
        for (int q = 0; q < 3; q++)
            CP_ASYNC16(dst + q*16, src + q*8, sz);
    }
}

__global__ __launch_bounds__(NTHR, 1)
void step_kernel(const float* __restrict__ bias, int t) {
    extern __shared__ unsigned char smem[];
    const uint32_t sbase = smem_to_u32(smem);
    const int tid  = threadIdx.x;
    const int w    = tid >> 5;
    const int lane = tid & 31;

    const __half* Ain_h = (t & 1) ? g_A1h : g_A0h;
    const __half* Ain_l = (t & 1) ? g_A1l : g_A0l;
    __half* Aout_h = (t & 1) ? g_A0h : g_A1h;
    __half* Aout_l = (t & 1) ? g_A0l : g_A1l;

    // ---- Stage B + bias once per CTA ----
    {
        const float4* gB = reinterpret_cast<const float4*>(g_B);
        float4* sB = reinterpret_cast<float4*>(smem + SM_B);
        #pragma unroll 4
        for (int i = tid; i < B_TOTAL_B/16; i += NTHR) sB[i] = gB[i];
        if (tid < 88) {
            int co = tid >> 2, g = tid & 3;
            reinterpret_cast<float*>(smem + SM_BIAS)[tid] =
                (co < Fc) ? bias[g*Fc + co] : 0.0f;
        }
        if (tid < 8)
            reinterpret_cast<uint32_t*>(smem + SM_HALO1 + BUF_B)[tid] = 0;
    }

    // ---- Warp tiling: 24 warps = 4my x 3mx x 2nhalf, warp tile m32 x n44 ----
    const int nhalf = w & 1;
    const int mx    = (w >> 1) % 3;
    const int my    = w / 6;
    const int mxb   = mx * 32;
    const int NF    = nhalf ? 5 : 6;
    const uint32_t aLane  = (uint32_t)(lane & 15)*48 + (uint32_t)((lane >> 4) & 1)*16;
    const uint32_t bLane4 = (uint32_t)(lane & 7)*496 + (uint32_t)((lane >> 3) & 1)*16
                          + (uint32_t)((lane >> 4) & 1)*(8*496);
    const uint32_t bLane2 = (uint32_t)(lane & 7)*496 + (uint32_t)((lane >> 3) & 1)*16;
    const uint32_t nOff   = (uint32_t)nhalf * (48*496);
    const float* sb_all = reinterpret_cast<const float*>(smem + SM_BIAS);

    // ---- Prologue: prefetch first tile ----
    int idx = blockIdx.x;
    if (idx < NTILES) {
        int b0 = idx / (NTX*NTY), r0 = idx % (NTX*NTY);
        prefetch_halo(sbase + SM_HALO0, b0, (r0 & 1)*TILE_W, (r0 >> 1)*TILE_H,
                      Ain_h, Ain_l, tid);
    }
    CP_COMMIT();

    int cur = 0;
    for (; idx < NTILES; idx += GRID) {
        CP_WAIT0();
        __syncthreads();

        int nxt = idx + GRID;
        if (nxt < NTILES) {
            int bn = nxt / (NTX*NTY), rn = nxt % (NTX*NTY);
            prefetch_halo(sbase + (cur ? SM_HALO0 : SM_HALO1),
                          bn, (rn & 1)*TILE_W, (rn >> 1)*TILE_H, Ain_h, Ain_l, tid);
        }
        CP_COMMIT();

        const int b  = idx / (NTX*NTY);
        const int rr = idx % (NTX*NTY);
        const int x0 = (rr & 1)*TILE_W;
        const int y0 = (rr >> 1)*TILE_H;
        const uint32_t Hbuf = sbase + (cur ? SM_HALO1 : SM_HALO0);

        // ---- Correction passes (f16 accum): cp0 = (Al,Bh), cp1 = (Ah,Bl) ----
        uint32_t e[2][6][2];
        #pragma unroll
        for (int mf = 0; mf < 2; mf++)
            #pragma unroll
            for (int nf = 0; nf < 6; nf++) { e[mf][nf][0] = 0u; e[mf][nf][1] = 0u; }

        #pragma unroll 1
        for (int cp = 0; cp < 2; cp++) {
            const uint32_t Ab = Hbuf + ((cp == 0) ? HPLANE_B : 0);
            const uint32_t Bb = sbase + SM_B + ((cp == 1) ? BPLANE_B : 0) + nOff;
            #pragma unroll 1
            for (int dy = 0; dy < 3; dy++) {
                const uint32_t Arow = Ab + (uint32_t)((my + dy)*HCOLS + mxb)*48 + aLane;
                const uint32_t Brow = Bb + (uint32_t)dy*160;
                #pragma unroll
                for (int c = 0; c < 5; c++) {
                    uint32_t bq[12];
                    {
                        const uint32_t ba4 = Brow + bLane4 + c*32;
                        LDSM_X4(bq[0], bq[1], bq[2], bq[3], ba4);
                        LDSM_X4(bq[4], bq[5], bq[6], bq[7], ba4 + 2*(8*496));
                        if (nhalf) {
                            LDSM_X2(bq[8], bq[9], Brow + bLane2 + 4*(8*496) + c*32);
                        } else {
                            LDSM_X4(bq[8], bq[9], bq[10], bq[11], ba4 + 4*(8*496));
                        }
                    }
                    #pragma unroll
                    for (int mf = 0; mf < 2; mf++) {
                        uint32_t a0, a1, a2, a3;
                        LDSM_X4(a0, a1, a2, a3, Arow + mf*(16*48) + c*32);
                        #pragma unroll
                        for (int nf = 0; nf < 6; nf++)
                            if (nf < NF)
                                MMA_F16(e[mf][nf], a0, a1, a2, a3, bq[2*nf], bq[2*nf+1]);
                    }
                }
            }
        }

        // ---- Convert corrections to f32 accumulators ----
        float d[2][6][4];
        #pragma unroll
        for (int mf = 0; mf < 2; mf++)
            #pragma unroll
            for (int nf = 0; nf < 6; nf++) {
                __half2 p0 = *reinterpret_cast<__half2*>(&e[mf][nf][0]);
                __half2 p1 = *reinterpret_cast<__half2*>(&e[mf][nf][1]);
                float2 f0 = __half22float2(p0);
                float2 f1 = __half22float2(p1);
                d[mf][nf][0] = f0.x; d[mf][nf][1] = f0.y;
                d[mf][nf][2] = f1.x; d[mf][nf][3] = f1.y;
            }

        // ---- Main pass (f32 accum): (Ah, Bh) ----
        {
            const uint32_t Ab = Hbuf;
            const uint32_t Bb = sbase + SM_B + nOff;
            #pragma unroll 1
            for (int dy = 0; dy < 3; dy++) {
                const uint32_t Arow = Ab + (uint32_t)((my + dy)*HCOLS + mxb)*48 + aLane;
                const uint32_t Brow = Bb + (uint32_t)dy*160;
                #pragma unroll
                for (int c = 0; c < 5; c++) {
                    uint32_t bq[12];
                    {
                        const uint32_t ba4 = Brow + bLane4 + c*32;
                        LDSM_X4(bq[0], bq[1], bq[2], bq[3], ba4);
                        LDSM_X4(bq[4], bq[5], bq[6], bq[7], ba4 + 2*(8*496));
                        if (nhalf) {
                            LDSM_X2(bq[8], bq[9], Brow + bLane2 + 4*(8*496) + c*32);
                        } else {
                            LDSM_X4(bq[8], bq[9], bq[10], bq[11], ba4 + 4*(8*496));
                        }
                    }
                    #pragma unroll
                    for (int mf = 0; mf < 2; mf++) {
                        uint32_t a0, a1, a2, a3;
                        LDSM_X4(a0, a1, a2, a3, Arow + mf*(16*48) + c*32);
                        #pragma unroll
                        for (int nf = 0; nf < 6; nf++)
                            if (nf < NF)
                                MMA_F32(d[mf][nf], a0, a1, a2, a3, bq[2*nf], bq[2*nf+1]);
                    }
                }
            }
        }

        // ---- Epilogue: gate update, write h into Aout ch-last slots 0..20 ----
        {
            const int gid    = lane >> 2;
            const int co_off = (lane >> 1) & 1;
            const bool lowrow = ((lane & 1) == 0);
            const int gy = y0 + my;
            const int cob = nhalf * 12;
            #pragma unroll
            for (int mf = 0; mf < 2; mf++) {
                #pragma unroll
                for (int nf = 0; nf < 6; nf++) {
                    if (nf >= NF) continue;
                    float* dd = d[mf][nf];
                    float r0 = __shfl_xor_sync(0xFFFFFFFFu, dd[0], 1);
                    float r1 = __shfl_xor_sync(0xFFFFFFFFu, dd[1], 1);
                    float r2 = __shfl_xor_sync(0xFFFFFFFFu, dd[2], 1);
                    float r3 = __shfl_xor_sync(0xFFFFFFFFu, dd[3], 1);
                    float zi, zf, zg, zo;
                    int rowm;
                    if (lowrow) { zi = dd[0]; zf = dd[1]; zg = r0;    zo = r1;    rowm = gid; }
                    else        { zi = r2;    zf = r3;    zg = dd[2]; zo = dd[3]; rowm = gid + 8; }
                    const int co = cob + 2*nf + co_off;
                    const int gx = x0 + mxb + mf*16 + rowm;
                    if (co < Fc && gx < Wc && gy < Hc) {
                        const float* sb = sb_all + co*4;
                        float ig = hsig(zi + sb[0]);
                        float fg = hsig(zf + sb[1]);
                        float gg = tanhf(zg + sb[2]);
                        float og = hsig(zo + sb[3]);
                        size_t pix = (size_t)gy*Wc + gx;
                        size_t cidx = ((size_t)(b*Fc + co))*HWc + pix;
                        float cn = fg * g_c[cidx] + ig * gg;
                        g_c[cidx] = cn;
                        float h = og * tanhf(cn);
                        __half hh = __float2half_rn(h);
                        size_t av = ((size_t)b*HWc + pix)*24 + co;
                        Aout_h[av] = hh;
                        Aout_l[av] = __float2half_rn(h - __half2float(hh));
                    }
                }
            }
            // x-forwarding: nhalf==1 warps write x(t+1) into slots 21..23
            if (nhalf) {
                const int t1 = t + 1;
                const int gy2 = y0 + my;
                for (int j = lane; j < 32*3; j += 32) {
                    int pxl = j / 3, ch = j - 3*pxl;
                    int gx = x0 + mxb + pxl;
                    if (gx < Wc && gy2 < Hc) {
                        size_t pix = (size_t)gy2*Wc + gx;
                        __half vh = __float2half_rn(0.0f), vl = vh;
                        if (t1 < Tc) {
                            size_t xi = ((size_t)((b*Tc + t1)*3 + ch))*HWc + pix;
                            vh = g_xh[xi];
                            vl = g_xl[xi];
                        }
                        size_t av = ((size_t)b*HWc + pix)*24 + 21 + ch;
                        Aout_h[av] = vh;
                        Aout_l[av] = vl;
                    }
                }
            }
        }
        cur ^= 1;
    }
}

// ===========================================================================
// out[b,h,w,co] = (A0h + A0l)[b][pix][co] * mask[pix]
// ===========================================================================
__global__ void mask_out_kernel(const float* __restrict__ mask, float* __restrict__ out) {
    const int n = Bc*HWc*Fc;
    int i = blockIdx.x*blockDim.x + threadIdx.x;
    if (i >= n) return;
    int co   = i % Fc;
    int rest = i / Fc;
    int p    = rest % HWc;
    int b    = rest / HWc;
    size_t av = ((size_t)b*HWc + p)*24 + co;
    float h = __half2float(g_A0h[av]) + __half2float(g_A0l[av]);
    out[i] = h * mask[p];
}

// ===========================================================================
extern "C" void kernel_launch(void* const* d_in, const int* in_sizes, int n_in,
                              void* d_out, int out_size) {
    const float* x     = (const float*)d_in[0];
    const float* kern  = (const float*)d_in[1];
    const float* rkern = (const float*)d_in[2];
    const float* bias  = (const float*)d_in[3];
    const float* mask  = (const float*)d_in[4];
    float* out = (float*)d_out;
    (void)in_sizes; (void)n_in; (void)out_size;

    cudaFuncSetAttribute(step_kernel, cudaFuncAttributeMaxDynamicSharedMemorySize,
                         SMEM_BYTES);

    init_kernel<<<2048, 256>>>(x);
    xsplit_kernel<<<4096, 256>>>(x);
    packB_kernel<<<(2*88*BROW + 255)/256, 256>>>(kern, rkern);

    for (int t = 0; t < Tc; t++) {
        step_kernel<<<GRID, NTHR, SMEM_BYTES>>>(bias, t);
    }

    const int n = Bc*HWc*Fc;
    mask_out_kernel<<<(n + 255)/256, 256>>>(mask, out);
}

// round 13
// speedup vs baseline: 1.3124x; 1.3124x over previous
#include <cuda_runtime.h>
#include <cuda_fp16.h>
#include <math.h>
#include <cstdint>

// ===========================================================================
// Problem constants
// ===========================================================================
#define Bc   16
#define Tc   16
#define Hc   161
#define Wc   181
#define HWc  (Hc*Wc)            // 29141
#define Fc   21
#define F4c  84

// Tile: M = 384 pixels (96 wide x 4 high), N = 88, K = 2x240 (fp16x2 passes)
// 24 warps: warp = m32 x n44 (4my x 3mx x 2nhalf)
#define TILE_W 96
#define TILE_H 4
#define NTX 2
#define NTY 41
#define NTILES (NTX*NTY*Bc)     // 1312
#define GRID 148

// B matrix: n-major [88][248] fp16, hi precision only (row 496 B, k pad zero)
#define BROW   248
#define B_TOTAL_B (88*BROW*2)       // 43,648

// Halo: channel-last [prec][6 rows][98 cols][24 ch] fp16 (prec: hi, lo)
#define HROWS 6
#define HCOLS 98
#define HCH   24
#define HPLANE_B (HROWS*HCOLS*HCH*2)   // 28,224
#define BUF_B (2*HPLANE_B)             // 56,448 per halo buffer

// SMEM layout
#define SM_B     0
#define SM_BIAS  B_TOTAL_B                      // 43,648
#define SM_HALO0 (SM_BIAS + 352)                // 44,000 (16B aligned)
#define SM_HALO1 (SM_HALO0 + BUF_B)             // 100,448
#define SMEM_BYTES (SM_HALO1 + BUF_B + 32)      // 156,928

#define NTHR 768

// Combined input arrays: [b][HW][24] ch-last; ch 0..20 = h, ch 21..23 = x(t)
#define ASZ (Bc*HWc*24)
#define CSZ (Bc*Fc*HWc)
#define XSZ (Bc*Tc*3*HWc)

// ===========================================================================
// Device globals
// ===========================================================================
__device__ __half g_B[88*BROW];
__device__ __align__(16) __half g_A0h[ASZ], g_A0l[ASZ];  // read at even t
__device__ __align__(16) __half g_A1h[ASZ], g_A1l[ASZ];  // read at odd t
__device__ float g_c[CSZ];
__device__ __half g_xh[XSZ], g_xl[XSZ];   // planar x hi/lo

// ===========================================================================
// PTX helpers (compute_103-safe)
// ===========================================================================
__device__ __forceinline__ uint32_t smem_to_u32(const void* p) {
    uint32_t a;
    asm("{ .reg .u64 t; cvta.to.shared.u64 t, %1; cvt.u32.u64 %0, t; }"
        : "=r"(a) : "l"(p));
    return a;
}
#define LDSM_X4(r0,r1,r2,r3,addr) \
    asm volatile("ldmatrix.sync.aligned.m8n8.x4.shared.b16 {%0,%1,%2,%3}, [%4];" \
        : "=r"(r0),"=r"(r1),"=r"(r2),"=r"(r3) : "r"(addr))
#define LDSM_X2(r0,r1,addr) \
    asm volatile("ldmatrix.sync.aligned.m8n8.x2.shared.b16 {%0,%1}, [%2];" \
        : "=r"(r0),"=r"(r1) : "r"(addr))
#define MMA_F32(d,a0,a1,a2,a3,b0,b1) \
    asm volatile("mma.sync.aligned.m16n8k16.row.col.f32.f16.f16.f32 " \
        "{%0,%1,%2,%3}, {%4,%5,%6,%7}, {%8,%9}, {%0,%1,%2,%3};" \
        : "+f"((d)[0]),"+f"((d)[1]),"+f"((d)[2]),"+f"((d)[3]) \
        : "r"(a0),"r"(a1),"r"(a2),"r"(a3),"r"(b0),"r"(b1))
#define CP_ASYNC16(dst, src, sz) \
    asm volatile("cp.async.ca.shared.global [%0], [%1], 16, %2;" \
        :: "r"(dst), "l"(src), "r"(sz) : "memory")
#define CP_COMMIT() asm volatile("cp.async.commit_group;" ::: "memory")
#define CP_WAIT0()  asm volatile("cp.async.wait_group 0;" ::: "memory")

__device__ __forceinline__ float hsig(float v) {
    return fminf(fmaxf(0.2f*v + 0.5f, 0.0f), 1.0f);
}

// ===========================================================================
// Aux kernels
// ===========================================================================
__global__ void init_kernel(const float* __restrict__ x) {
    for (int i = blockIdx.x*blockDim.x + threadIdx.x; i < ASZ; i += gridDim.x*blockDim.x) {
        int ch = i % 24;
        int p  = (i / 24) % HWc;
        int b  = i / (24*HWc);
        __half vh = __float2half_rn(0.0f), vl = vh;
        if (ch >= 21) {
            float v = x[(((size_t)(b*Tc)*HWc) + p)*3 + (ch - 21)];
            vh = __float2half_rn(v);
            vl = __float2half_rn(v - __half2float(vh));
        }
        g_A0h[i] = vh;
        g_A0l[i] = vl;
    }
    for (int i = blockIdx.x*blockDim.x + threadIdx.x; i < CSZ; i += gridDim.x*blockDim.x)
        g_c[i] = 0.0f;
}

__global__ void xsplit_kernel(const float* __restrict__ x) {
    for (int i = blockIdx.x*blockDim.x + threadIdx.x; i < XSZ; i += gridDim.x*blockDim.x) {
        int p  = i % HWc;
        int r  = i / HWc;
        int c  = r % 3;
        int bt = r / 3;
        float v = x[((size_t)bt*HWc + p)*3 + c];
        __half hi = __float2half_rn(v);
        g_xh[i] = hi;
        g_xl[i] = __float2half_rn(v - __half2float(hi));
    }
}

// Pack weights (hi precision only): B[n][k], n = 4*co+g, k = dy*80 + dx*24 + cin
// cin: 0..20 = h (rkern), 21..23 = x (kern); k%80>=72 and k>=240 zero pad
__global__ void packB_kernel(const float* __restrict__ kern, const float* __restrict__ rkern) {
    int i = blockIdx.x*blockDim.x + threadIdx.x;
    const int TOT = 88*BROW;
    if (i >= TOT) return;
    int n    = i / BROW;
    int k    = i - n*BROW;
    int co = n >> 2, g = n & 3;
    float w = 0.0f;
    if (k < 240 && co < Fc) {
        int dy = k / 80, r2 = k - dy*80;
        if (r2 < 72) {
            int dx = r2 / 24, cin = r2 - dx*24;
            int col = g*Fc + co;
            if (cin < 21) w = rkern[((dy*3 + dx)*Fc + cin     )*F4c + col];
            else          w = kern [((dy*3 + dx)*3  + (cin-21))*F4c + col];
        }
    }
    g_B[i] = __float2half_rn(w);
}

// ===========================================================================
// Persistent step kernel: 24 warps (m32n44), fp16x2 HMMA (Ah*Bh + Al*Bh)
// ===========================================================================
__device__ __forceinline__ void prefetch_halo(
    uint32_t dstbase, int b, int x0, int y0,
    const __half* __restrict__ Ah, const __half* __restrict__ Al,
    int tid) {
    const int TOTE = 2*HROWS*HCOLS;     // 1176 pixel-entries
    for (int i = tid; i < TOTE; i += NTHR) {
        int c = i % HCOLS;
        int r = (i / HCOLS) % HROWS;
        int p = i / (HCOLS*HROWS);
        int gy = y0 + r - 1, gx = x0 + c - 1;
        bool ok = ((unsigned)gy < (unsigned)Hc) && ((unsigned)gx < (unsigned)Wc);
        size_t off = ok ? ((size_t)b*HWc + (size_t)gy*Wc + gx)*24 : 0;
        const __half* src = (p ? Al : Ah) + off;
        uint32_t dst = dstbase + (uint32_t)p*HPLANE_B + (uint32_t)(r*HCOLS + c)*48;
        uint32_t sz = ok ? 16u : 0u;
        #pragma unroll
        for (int q = 0; q < 3; q++)
            CP_ASYNC16(dst + q*16, src + q*8, sz);
    }
}

__global__ __launch_bounds__(NTHR, 1)
void step_kernel(const float* __restrict__ bias, int t) {
    extern __shared__ unsigned char smem[];
    const uint32_t sbase = smem_to_u32(smem);
    const int tid  = threadIdx.x;
    const int w    = tid >> 5;
    const int lane = tid & 31;

    const __half* Ain_h = (t & 1) ? g_A1h : g_A0h;
    const __half* Ain_l = (t & 1) ? g_A1l : g_A0l;
    __half* Aout_h = (t & 1) ? g_A0h : g_A1h;
    __half* Aout_l = (t & 1) ? g_A0l : g_A1l;

    // ---- Stage B + bias once per CTA ----
    {
        const float4* gB = reinterpret_cast<const float4*>(g_B);
        float4* sB = reinterpret_cast<float4*>(smem + SM_B);
        #pragma unroll 4
        for (int i = tid; i < B_TOTAL_B/16; i += NTHR) sB[i] = gB[i];
        if (tid < 88) {
            int co = tid >> 2, g = tid & 3;
            reinterpret_cast<float*>(smem + SM_BIAS)[tid] =
                (co < Fc) ? bias[g*Fc + co] : 0.0f;
        }
        if (tid < 8)
            reinterpret_cast<uint32_t*>(smem + SM_HALO1 + BUF_B)[tid] = 0;
    }

    // ---- Warp tiling: 24 warps = 4my x 3mx x 2nhalf, warp tile m32 x n44 ----
    const int nhalf = w & 1;
    const int mx    = (w >> 1) % 3;
    const int my    = w / 6;
    const int mxb   = mx * 32;
    const int NF    = nhalf ? 5 : 6;
    const uint32_t aLane  = (uint32_t)(lane & 15)*48 + (uint32_t)((lane >> 4) & 1)*16;
    const uint32_t bLane4 = (uint32_t)(lane & 7)*496 + (uint32_t)((lane >> 3) & 1)*16
                          + (uint32_t)((lane >> 4) & 1)*(8*496);
    const uint32_t bLane2 = (uint32_t)(lane & 7)*496 + (uint32_t)((lane >> 3) & 1)*16;
    const uint32_t nOff   = (uint32_t)nhalf * (48*496);
    const float* sb_all = reinterpret_cast<const float*>(smem + SM_BIAS);

    // ---- Prologue: prefetch first tile ----
    int idx = blockIdx.x;
    if (idx < NTILES) {
        int b0 = idx / (NTX*NTY), r0 = idx % (NTX*NTY);
        prefetch_halo(sbase + SM_HALO0, b0, (r0 & 1)*TILE_W, (r0 >> 1)*TILE_H,
                      Ain_h, Ain_l, tid);
    }
    CP_COMMIT();

    int cur = 0;
    for (; idx < NTILES; idx += GRID) {
        CP_WAIT0();
        __syncthreads();

        int nxt = idx + GRID;
        if (nxt < NTILES) {
            int bn = nxt / (NTX*NTY), rn = nxt % (NTX*NTY);
            prefetch_halo(sbase + (cur ? SM_HALO0 : SM_HALO1),
                          bn, (rn & 1)*TILE_W, (rn >> 1)*TILE_H, Ain_h, Ain_l, tid);
        }
        CP_COMMIT();

        const int b  = idx / (NTX*NTY);
        const int rr = idx % (NTX*NTY);
        const int x0 = (rr & 1)*TILE_W;
        const int y0 = (rr >> 1)*TILE_H;
        const uint32_t Hbuf = sbase + (cur ? SM_HALO1 : SM_HALO0);

        // ---- Mainloop: 2 passes, f32 accum: (Al,Bh) then (Ah,Bh) ----
        float d[2][6][4];
        #pragma unroll
        for (int mf = 0; mf < 2; mf++)
            #pragma unroll
            for (int nf = 0; nf < 6; nf++)
                #pragma unroll
                for (int q = 0; q < 4; q++) d[mf][nf][q] = 0.0f;

        #pragma unroll 1
        for (int ps = 0; ps < 2; ps++) {
            const uint32_t Ab = Hbuf + ((ps == 0) ? HPLANE_B : 0);  // Al first
            const uint32_t Bb = sbase + SM_B + nOff;
            #pragma unroll 1
            for (int dy = 0; dy < 3; dy++) {
                const uint32_t Arow = Ab + (uint32_t)((my + dy)*HCOLS + mxb)*48 + aLane;
                const uint32_t Brow = Bb + (uint32_t)dy*160;
                #pragma unroll
                for (int c = 0; c < 5; c++) {
                    uint32_t bq[12];
                    {
                        const uint32_t ba4 = Brow + bLane4 + c*32;
                        LDSM_X4(bq[0], bq[1], bq[2], bq[3], ba4);
                        LDSM_X4(bq[4], bq[5], bq[6], bq[7], ba4 + 2*(8*496));
                        if (nhalf) {
                            LDSM_X2(bq[8], bq[9], Brow + bLane2 + 4*(8*496) + c*32);
                        } else {
                            LDSM_X4(bq[8], bq[9], bq[10], bq[11], ba4 + 4*(8*496));
                        }
                    }
                    #pragma unroll
                    for (int mf = 0; mf < 2; mf++) {
                        uint32_t a0, a1, a2, a3;
                        LDSM_X4(a0, a1, a2, a3, Arow + mf*(16*48) + c*32);
                        #pragma unroll
                        for (int nf = 0; nf < 6; nf++)
                            if (nf < NF)
                                MMA_F32(d[mf][nf], a0, a1, a2, a3, bq[2*nf], bq[2*nf+1]);
                    }
                }
            }
        }

        // ---- Epilogue: gate update, write h into Aout ch-last slots 0..20 ----
        {
            const int gid    = lane >> 2;
            const int co_off = (lane >> 1) & 1;
            const bool lowrow = ((lane & 1) == 0);
            const int gy = y0 + my;
            const int cob = nhalf * 12;
            #pragma unroll
            for (int mf = 0; mf < 2; mf++) {
                #pragma unroll
                for (int nf = 0; nf < 6; nf++) {
                    if (nf >= NF) continue;
                    float* dd = d[mf][nf];
                    float r0 = __shfl_xor_sync(0xFFFFFFFFu, dd[0], 1);
                    float r1 = __shfl_xor_sync(0xFFFFFFFFu, dd[1], 1);
                    float r2 = __shfl_xor_sync(0xFFFFFFFFu, dd[2], 1);
                    float r3 = __shfl_xor_sync(0xFFFFFFFFu, dd[3], 1);
                    float zi, zf, zg, zo;
                    int rowm;
                    if (lowrow) { zi = dd[0]; zf = dd[1]; zg = r0;    zo = r1;    rowm = gid; }
                    else        { zi = r2;    zf = r3;    zg = dd[2]; zo = dd[3]; rowm = gid + 8; }
                    const int co = cob + 2*nf + co_off;
                    const int gx = x0 + mxb + mf*16 + rowm;
                    if (co < Fc && gx < Wc && gy < Hc) {
                        const float* sb = sb_all + co*4;
                        float ig = hsig(zi + sb[0]);
                        float fg = hsig(zf + sb[1]);
                        float gg = tanhf(zg + sb[2]);
                        float og = hsig(zo + sb[3]);
                        size_t pix = (size_t)gy*Wc + gx;
                        size_t cidx = ((size_t)(b*Fc + co))*HWc + pix;
                        float cn = fg * g_c[cidx] + ig * gg;
                        g_c[cidx] = cn;
                        float h = og * tanhf(cn);
                        __half hh = __float2half_rn(h);
                        size_t av = ((size_t)b*HWc + pix)*24 + co;
                        Aout_h[av] = hh;
                        Aout_l[av] = __float2half_rn(h - __half2float(hh));
                    }
                }
            }
            // x-forwarding: nhalf==1 warps write x(t+1) into slots 21..23
            if (nhalf) {
                const int t1 = t + 1;
                const int gy2 = y0 + my;
                for (int j = lane; j < 32*3; j += 32) {
                    int pxl = j / 3, ch = j - 3*pxl;
                    int gx = x0 + mxb + pxl;
                    if (gx < Wc && gy2 < Hc) {
                        size_t pix = (size_t)gy2*Wc + gx;
                        __half vh = __float2half_rn(0.0f), vl = vh;
                        if (t1 < Tc) {
                            size_t xi = ((size_t)((b*Tc + t1)*3 + ch))*HWc + pix;
                            vh = g_xh[xi];
                            vl = g_xl[xi];
                        }
                        size_t av = ((size_t)b*HWc + pix)*24 + 21 + ch;
                        Aout_h[av] = vh;
                        Aout_l[av] = vl;
                    }
                }
            }
        }
        cur ^= 1;
    }
}

// ===========================================================================
// out[b,h,w,co] = (A0h + A0l)[b][pix][co] * mask[pix]
// ===========================================================================
__global__ void mask_out_kernel(const float* __restrict__ mask, float* __restrict__ out) {
    const int n = Bc*HWc*Fc;
    int i = blockIdx.x*blockDim.x + threadIdx.x;
    if (i >= n) return;
    int co   = i % Fc;
    int rest = i / Fc;
    int p    = rest % HWc;
    int b    = rest / HWc;
    size_t av = ((size_t)b*HWc + p)*24 + co;
    float h = __half2float(g_A0h[av]) + __half2float(g_A0l[av]);
    out[i] = h * mask[p];
}

// ===========================================================================
extern "C" void kernel_launch(void* const* d_in, const int* in_sizes, int n_in,
                              void* d_out, int out_size) {
    const float* x     = (const float*)d_in[0];
    const float* kern  = (const float*)d_in[1];
    const float* rkern = (const float*)d_in[2];
    const float* bias  = (const float*)d_in[3];
    const float* mask  = (const float*)d_in[4];
    float* out = (float*)d_out;
    (void)in_sizes; (void)n_in; (void)out_size;

    cudaFuncSetAttribute(step_kernel, cudaFuncAttributeMaxDynamicSharedMemorySize,
                         SMEM_BYTES);

    init_kernel<<<2048, 256>>>(x);
    xsplit_kernel<<<4096, 256>>>(x);
    packB_kernel<<<(88*BROW + 255)/256, 256>>>(kern, rkern);

    for (int t = 0; t < Tc; t++) {
        step_kernel<<<GRID, NTHR, SMEM_BYTES>>>(bias, t);
    }

    const int n = Bc*HWc*Fc;
    mask_out_kernel<<<(n + 255)/256, 256>>>(mask, out);
}

// round 14
// speedup vs baseline: 2.0916x; 1.5937x over previous
#include <cuda_runtime.h>
#include <cuda_fp16.h>
#include <math.h>
#include <cstdint>

// ===========================================================================
// Problem constants
// ===========================================================================
#define Bc   16
#define Tc   16
#define Hc   161
#define Wc   181
#define HWc  (Hc*Wc)            // 29141
#define Fc   21
#define F4c  84

// Tile: M = 384 pixels (96 wide x 4 high), N = 88, K = 240 (single fp16 pass)
// 24 warps: warp = m32 x n44 (4my x 3mx x 2nhalf)
#define TILE_W 96
#define TILE_H 4
#define NTX 2
#define NTY 41
#define NTILES (NTX*NTY*Bc)     // 1312
#define GRID 148

// B matrix: n-major [88][248] fp16 (row 496 B, k pad zero)
#define BROW   248
#define B_TOTAL_B (88*BROW*2)       // 43,648

// Halo: channel-last [6 rows][98 cols][24 ch] fp16, single precision plane
#define HROWS 6
#define HCOLS 98
#define HCH   24
#define HPLANE_B (HROWS*HCOLS*HCH*2)   // 28,224 per halo buffer

// SMEM layout
#define SM_B     0
#define SM_BIAS  B_TOTAL_B                      // 43,648
#define SM_HALO0 (SM_BIAS + 352)                // 44,000 (16B aligned)
#define SM_HALO1 (SM_HALO0 + HPLANE_B)          // 72,224
#define SMEM_BYTES (SM_HALO1 + HPLANE_B + 32)   // 100,480

#define NTHR 768

// Combined input arrays: [b][HW][24] ch-last; ch 0..20 = h, ch 21..23 = x(t)
#define ASZ (Bc*HWc*24)
#define CSZ (Bc*Fc*HWc)
#define XSZ (Bc*Tc*3*HWc)

// ===========================================================================
// Device globals
// ===========================================================================
__device__ __half g_B[88*BROW];
__device__ __align__(16) __half g_A0[ASZ];  // read at even t
__device__ __align__(16) __half g_A1[ASZ];  // read at odd t
__device__ float g_c[CSZ];
__device__ __half g_x[XSZ];                 // planar x fp16

// ===========================================================================
// PTX helpers (compute_103-safe)
// ===========================================================================
__device__ __forceinline__ uint32_t smem_to_u32(const void* p) {
    uint32_t a;
    asm("{ .reg .u64 t; cvta.to.shared.u64 t, %1; cvt.u32.u64 %0, t; }"
        : "=r"(a) : "l"(p));
    return a;
}
#define LDSM_X4(r0,r1,r2,r3,addr) \
    asm volatile("ldmatrix.sync.aligned.m8n8.x4.shared.b16 {%0,%1,%2,%3}, [%4];" \
        : "=r"(r0),"=r"(r1),"=r"(r2),"=r"(r3) : "r"(addr))
#define LDSM_X2(r0,r1,addr) \
    asm volatile("ldmatrix.sync.aligned.m8n8.x2.shared.b16 {%0,%1}, [%2];" \
        : "=r"(r0),"=r"(r1) : "r"(addr))
#define MMA_F32(d,a0,a1,a2,a3,b0,b1) \
    asm volatile("mma.sync.aligned.m16n8k16.row.col.f32.f16.f16.f32 " \
        "{%0,%1,%2,%3}, {%4,%5,%6,%7}, {%8,%9}, {%0,%1,%2,%3};" \
        : "+f"((d)[0]),"+f"((d)[1]),"+f"((d)[2]),"+f"((d)[3]) \
        : "r"(a0),"r"(a1),"r"(a2),"r"(a3),"r"(b0),"r"(b1))
#define CP_ASYNC16(dst, src, sz) \
    asm volatile("cp.async.ca.shared.global [%0], [%1], 16, %2;" \
        :: "r"(dst), "l"(src), "r"(sz) : "memory")
#define CP_COMMIT() asm volatile("cp.async.commit_group;" ::: "memory")
#define CP_WAIT0()  asm volatile("cp.async.wait_group 0;" ::: "memory")

__device__ __forceinline__ float hsig(float v) {
    return fminf(fmaxf(0.2f*v + 0.5f, 0.0f), 1.0f);
}

// ===========================================================================
// Aux kernels
// ===========================================================================
__global__ void init_kernel(const float* __restrict__ x) {
    for (int i = blockIdx.x*blockDim.x + threadIdx.x; i < ASZ; i += gridDim.x*blockDim.x) {
        int ch = i % 24;
        int p  = (i / 24) % HWc;
        int b  = i / (24*HWc);
        __half v = __float2half_rn(0.0f);
        if (ch >= 21)
            v = __float2half_rn(x[(((size_t)(b*Tc)*HWc) + p)*3 + (ch - 21)]);
        g_A0[i] = v;
    }
    for (int i = blockIdx.x*blockDim.x + threadIdx.x; i < CSZ; i += gridDim.x*blockDim.x)
        g_c[i] = 0.0f;
}

__global__ void xsplit_kernel(const float* __restrict__ x) {
    for (int i = blockIdx.x*blockDim.x + threadIdx.x; i < XSZ; i += gridDim.x*blockDim.x) {
        int p  = i % HWc;
        int r  = i / HWc;
        int c  = r % 3;
        int bt = r / 3;
        g_x[i] = __float2half_rn(x[((size_t)bt*HWc + p)*3 + c]);
    }
}

// Pack weights: B[n][k], n = 4*co+g, k = dy*80 + dx*24 + cin
// cin: 0..20 = h (rkern), 21..23 = x (kern); k%80>=72 and k>=240 zero pad
__global__ void packB_kernel(const float* __restrict__ kern, const float* __restrict__ rkern) {
    int i = blockIdx.x*blockDim.x + threadIdx.x;
    const int TOT = 88*BROW;
    if (i >= TOT) return;
    int n    = i / BROW;
    int k    = i - n*BROW;
    int co = n >> 2, g = n & 3;
    float w = 0.0f;
    if (k < 240 && co < Fc) {
        int dy = k / 80, r2 = k - dy*80;
        if (r2 < 72) {
            int dx = r2 / 24, cin = r2 - dx*24;
            int col = g*Fc + co;
            if (cin < 21) w = rkern[((dy*3 + dx)*Fc + cin     )*F4c + col];
            else          w = kern [((dy*3 + dx)*3  + (cin-21))*F4c + col];
        }
    }
    g_B[i] = __float2half_rn(w);
}

// ===========================================================================
// Persistent step kernel: 24 warps (m32n44), single-pass fp16 HMMA
// ===========================================================================
__device__ __forceinline__ void prefetch_halo(
    uint32_t dstbase, int b, int x0, int y0,
    const __half* __restrict__ A, int tid) {
    const int TOTE = HROWS*HCOLS;     // 588 pixel-entries
    for (int i = tid; i < TOTE; i += NTHR) {
        int c = i % HCOLS;
        int r = i / HCOLS;
        int gy = y0 + r - 1, gx = x0 + c - 1;
        bool ok = ((unsigned)gy < (unsigned)Hc) && ((unsigned)gx < (unsigned)Wc);
        size_t off = ok ? ((size_t)b*HWc + (size_t)gy*Wc + gx)*24 : 0;
        const __half* src = A + off;
        uint32_t dst = dstbase + (uint32_t)(r*HCOLS + c)*48;
        uint32_t sz = ok ? 16u : 0u;
        #pragma unroll
        for (int q = 0; q < 3; q++)
            CP_ASYNC16(dst + q*16, src + q*8, sz);
    }
}

__global__ __launch_bounds__(NTHR, 1)
void step_kernel(const float* __restrict__ bias, int t) {
    extern __shared__ unsigned char smem[];
    const uint32_t sbase = smem_to_u32(smem);
    const int tid  = threadIdx.x;
    const int w    = tid >> 5;
    const int lane = tid & 31;

    const __half* Ain = (t & 1) ? g_A1 : g_A0;
    __half*       Aout = (t & 1) ? g_A0 : g_A1;

    // ---- Stage B + bias once per CTA ----
    {
        const float4* gB = reinterpret_cast<const float4*>(g_B);
        float4* sB = reinterpret_cast<float4*>(smem + SM_B);
        #pragma unroll 4
        for (int i = tid; i < B_TOTAL_B/16; i += NTHR) sB[i] = gB[i];
        if (tid < 88) {
            int co = tid >> 2, g = tid & 3;
            reinterpret_cast<float*>(smem + SM_BIAS)[tid] =
                (co < Fc) ? bias[g*Fc + co] : 0.0f;
        }
        if (tid < 8)
            reinterpret_cast<uint32_t*>(smem + SM_HALO1 + HPLANE_B)[tid] = 0;
    }

    // ---- Warp tiling: 24 warps = 4my x 3mx x 2nhalf, warp tile m32 x n44 ----
    const int nhalf = w & 1;
    const int mx    = (w >> 1) % 3;
    const int my    = w / 6;
    const int mxb   = mx * 32;
    const int NF    = nhalf ? 5 : 6;
    const uint32_t aLane  = (uint32_t)(lane & 15)*48 + (uint32_t)((lane >> 4) & 1)*16;
    const uint32_t bLane4 = (uint32_t)(lane & 7)*496 + (uint32_t)((lane >> 3) & 1)*16
                          + (uint32_t)((lane >> 4) & 1)*(8*496);
    const uint32_t bLane2 = (uint32_t)(lane & 7)*496 + (uint32_t)((lane >> 3) & 1)*16;
    const uint32_t nOff   = (uint32_t)nhalf * (48*496);
    const float* sb_all = reinterpret_cast<const float*>(smem + SM_BIAS);

    // ---- Prologue: prefetch first tile ----
    int idx = blockIdx.x;
    if (idx < NTILES) {
        int b0 = idx / (NTX*NTY), r0 = idx % (NTX*NTY);
        prefetch_halo(sbase + SM_HALO0, b0, (r0 & 1)*TILE_W, (r0 >> 1)*TILE_H,
                      Ain, tid);
    }
    CP_COMMIT();

    int cur = 0;
    for (; idx < NTILES; idx += GRID) {
        CP_WAIT0();
        __syncthreads();

        int nxt = idx + GRID;
        if (nxt < NTILES) {
            int bn = nxt / (NTX*NTY), rn = nxt % (NTX*NTY);
            prefetch_halo(sbase + (cur ? SM_HALO0 : SM_HALO1),
                          bn, (rn & 1)*TILE_W, (rn >> 1)*TILE_H, Ain, tid);
        }
        CP_COMMIT();

        const int b  = idx / (NTX*NTY);
        const int rr = idx % (NTX*NTY);
        const int x0 = (rr & 1)*TILE_W;
        const int y0 = (rr >> 1)*TILE_H;
        const uint32_t Hbuf = sbase + (cur ? SM_HALO1 : SM_HALO0);

        // ---- Mainloop: single pass, f32 accum ----
        float d[2][6][4];
        #pragma unroll
        for (int mf = 0; mf < 2; mf++)
            #pragma unroll
            for (int nf = 0; nf < 6; nf++)
                #pragma unroll
                for (int q = 0; q < 4; q++) d[mf][nf][q] = 0.0f;

        {
            const uint32_t Bb = sbase + SM_B + nOff;
            #pragma unroll 1
            for (int dy = 0; dy < 3; dy++) {
                const uint32_t Arow = Hbuf + (uint32_t)((my + dy)*HCOLS + mxb)*48 + aLane;
                const uint32_t Brow = Bb + (uint32_t)dy*160;
                #pragma unroll
                for (int c = 0; c < 5; c++) {
                    uint32_t bq[12];
                    {
                        const uint32_t ba4 = Brow + bLane4 + c*32;
                        LDSM_X4(bq[0], bq[1], bq[2], bq[3], ba4);
                        LDSM_X4(bq[4], bq[5], bq[6], bq[7], ba4 + 2*(8*496));
                        if (nhalf) {
                            LDSM_X2(bq[8], bq[9], Brow + bLane2 + 4*(8*496) + c*32);
                        } else {
                            LDSM_X4(bq[8], bq[9], bq[10], bq[11], ba4 + 4*(8*496));
                        }
                    }
                    #pragma unroll
                    for (int mf = 0; mf < 2; mf++) {
                        uint32_t a0, a1, a2, a3;
                        LDSM_X4(a0, a1, a2, a3, Arow + mf*(16*48) + c*32);
                        #pragma unroll
                        for (int nf = 0; nf < 6; nf++)
                            if (nf < NF)
                                MMA_F32(d[mf][nf], a0, a1, a2, a3, bq[2*nf], bq[2*nf+1]);
                    }
                }
            }
        }

        // ---- Epilogue: gate update, write h into Aout ch-last slots 0..20 ----
        {
            const int gid    = lane >> 2;
            const int co_off = (lane >> 1) & 1;
            const bool lowrow = ((lane & 1) == 0);
            const int gy = y0 + my;
            const int cob = nhalf * 12;
            #pragma unroll
            for (int mf = 0; mf < 2; mf++) {
                #pragma unroll
                for (int nf = 0; nf < 6; nf++) {
                    if (nf >= NF) continue;
                    float* dd = d[mf][nf];
                    float r0 = __shfl_xor_sync(0xFFFFFFFFu, dd[0], 1);
                    float r1 = __shfl_xor_sync(0xFFFFFFFFu, dd[1], 1);
                    float r2 = __shfl_xor_sync(0xFFFFFFFFu, dd[2], 1);
                    float r3 = __shfl_xor_sync(0xFFFFFFFFu, dd[3], 1);
                    float zi, zf, zg, zo;
                    int rowm;
                    if (lowrow) { zi = dd[0]; zf = dd[1]; zg = r0;    zo = r1;    rowm = gid; }
                    else        { zi = r2;    zf = r3;    zg = dd[2]; zo = dd[3]; rowm = gid + 8; }
                    const int co = cob + 2*nf + co_off;
                    const int gx = x0 + mxb + mf*16 + rowm;
                    if (co < Fc && gx < Wc && gy < Hc) {
                        const float* sb = sb_all + co*4;
                        float ig = hsig(zi + sb[0]);
                        float fg = hsig(zf + sb[1]);
                        float gg = tanhf(zg + sb[2]);
                        float og = hsig(zo + sb[3]);
                        size_t pix = (size_t)gy*Wc + gx;
                        size_t cidx = ((size_t)(b*Fc + co))*HWc + pix;
                        float cn = fg * g_c[cidx] + ig * gg;
                        g_c[cidx] = cn;
                        float h = og * tanhf(cn);
                        size_t av = ((size_t)b*HWc + pix)*24 + co;
                        Aout[av] = __float2half_rn(h);
                    }
                }
            }
            // x-forwarding: nhalf==1 warps write x(t+1) into slots 21..23
            if (nhalf) {
                const int t1 = t + 1;
                const int gy2 = y0 + my;
                for (int j = lane; j < 32*3; j += 32) {
                    int pxl = j / 3, ch = j - 3*pxl;
                    int gx = x0 + mxb + pxl;
                    if (gx < Wc && gy2 < Hc) {
                        size_t pix = (size_t)gy2*Wc + gx;
                        __half v = __float2half_rn(0.0f);
                        if (t1 < Tc)
                            v = g_x[((size_t)((b*Tc + t1)*3 + ch))*HWc + pix];
                        Aout[((size_t)b*HWc + pix)*24 + 21 + ch] = v;
                    }
                }
            }
        }
        cur ^= 1;
    }
}

// ===========================================================================
// out[b,h,w,co] = A0[b][pix][co] * mask[pix]
// ===========================================================================
__global__ void mask_out_kernel(const float* __restrict__ mask, float* __restrict__ out) {
    const int n = Bc*HWc*Fc;
    int i = blockIdx.x*blockDim.x + threadIdx.x;
    if (i >= n) return;
    int co   = i % Fc;
    int rest = i / Fc;
    int p    = rest % HWc;
    int b    = rest / HWc;
    out[i] = __half2float(g_A0[((size_t)b*HWc + p)*24 + co]) * mask[p];
}

// ===========================================================================
extern "C" void kernel_launch(void* const* d_in, const int* in_sizes, int n_in,
                              void* d_out, int out_size) {
    const float* x     = (const float*)d_in[0];
    const float* kern  = (const float*)d_in[1];
    const float* rkern = (const float*)d_in[2];
    const float* bias  = (const float*)d_in[3];
    const float* mask  = (const float*)d_in[4];
    float* out = (float*)d_out;
    (void)in_sizes; (void)n_in; (void)out_size;

    cudaFuncSetAttribute(step_kernel, cudaFuncAttributeMaxDynamicSharedMemorySize,
                         SMEM_BYTES);

    init_kernel<<<2048, 256>>>(x);
    xsplit_kernel<<<4096, 256>>>(x);
    packB_kernel<<<(88*BROW + 255)/256, 256>>>(kern, rkern);

    for (int t = 0; t < Tc; t++) {
        step_kernel<<<GRID, NTHR, SMEM_BYTES>>>(bias, t);
    }

    const int n = Bc*HWc*Fc;
    mask_out_kernel<<<(n + 255)/256, 256>>>(mask, out);
}

// round 15
// speedup vs baseline: 2.2893x; 1.0945x over previous
#include <cuda_runtime.h>
#include <cuda_fp16.h>
#include <math.h>
#include <cstdint>

// ===========================================================================
// Problem constants
// ===========================================================================
#define Bc   16
#define Tc   16
#define Hc   161
#define Wc   181
#define HWc  (Hc*Wc)            // 29141
#define Fc   21
#define F4c  84

// Tile: M = 384 pixels (96 wide x 4 high), N = 88, K = 240 (single fp16 pass)
// 24 warps: warp = m32 x n44 (4my x 3mx x 2nhalf)
#define TILE_W 96
#define TILE_H 4
#define NTX 2
#define NTY 41
#define NTILES (NTX*NTY*Bc)     // 1312
#define GRID 148

// B matrix: n-major [88][248] fp16 (row 496 B, k pad zero)
#define BROW   248
#define B_TOTAL_B (88*BROW*2)       // 43,648

// Halo: channel-last [6 rows][98 cols][24 ch] fp16, single precision plane
#define HROWS 6
#define HCOLS 98
#define HCH   24
#define HPLANE_B (HROWS*HCOLS*HCH*2)   // 28,224 per halo buffer

// c tile in smem: [21 co][4 rows][96 px] f32
#define CTILE_B (Fc*TILE_H*TILE_W*4)   // 32,256

// SMEM layout
#define SM_B     0
#define SM_BIAS  B_TOTAL_B                      // 43,648
#define SM_HALO0 (SM_BIAS + 352)                // 44,000 (16B aligned)
#define SM_HALO1 (SM_HALO0 + HPLANE_B)          // 72,224
#define SM_C0    (SM_HALO1 + HPLANE_B + 32)     // 100,480 (32B zero pad before)
#define SM_C1    (SM_C0 + CTILE_B)              // 132,736
#define SMEM_BYTES (SM_C1 + CTILE_B)            // 164,992

#define NTHR 768

// Combined input arrays: [b][HW][24] ch-last; ch 0..20 = h, ch 21..23 = x(t)
#define ASZ (Bc*HWc*24)
#define XSZ (Bc*Tc*3*HWc)
// Padded c layout: [b][41 ty][21 co][4 rows][192 px] f32
#define CROWP 192
#define CSZP (Bc*NTY*Fc*TILE_H*CROWP)   // 10,579,968 floats

// ===========================================================================
// Device globals
// ===========================================================================
__device__ __half g_B[88*BROW];
__device__ __align__(16) __half g_A0[ASZ];  // read at even t
__device__ __align__(16) __half g_A1[ASZ];  // read at odd t
__device__ __align__(16) float g_c[CSZP];   // padded tile layout
__device__ __half g_x[XSZ];                 // planar x fp16

// ===========================================================================
// PTX helpers (compute_103-safe)
// ===========================================================================
__device__ __forceinline__ uint32_t smem_to_u32(const void* p) {
    uint32_t a;
    asm("{ .reg .u64 t; cvta.to.shared.u64 t, %1; cvt.u32.u64 %0, t; }"
        : "=r"(a) : "l"(p));
    return a;
}
#define LDSM_X4(r0,r1,r2,r3,addr) \
    asm volatile("ldmatrix.sync.aligned.m8n8.x4.shared.b16 {%0,%1,%2,%3}, [%4];" \
        : "=r"(r0),"=r"(r1),"=r"(r2),"=r"(r3) : "r"(addr))
#define LDSM_X2(r0,r1,addr) \
    asm volatile("ldmatrix.sync.aligned.m8n8.x2.shared.b16 {%0,%1}, [%2];" \
        : "=r"(r0),"=r"(r1) : "r"(addr))
#define MMA_F32(d,a0,a1,a2,a3,b0,b1) \
    asm volatile("mma.sync.aligned.m16n8k16.row.col.f32.f16.f16.f32 " \
        "{%0,%1,%2,%3}, {%4,%5,%6,%7}, {%8,%9}, {%0,%1,%2,%3};" \
        : "+f"((d)[0]),"+f"((d)[1]),"+f"((d)[2]),"+f"((d)[3]) \
        : "r"(a0),"r"(a1),"r"(a2),"r"(a3),"r"(b0),"r"(b1))
#define CP_ASYNC16(dst, src, sz) \
    asm volatile("cp.async.ca.shared.global [%0], [%1], 16, %2;" \
        :: "r"(dst), "l"(src), "r"(sz) : "memory")
#define CP_COMMIT() asm volatile("cp.async.commit_group;" ::: "memory")
#define CP_WAIT0()  asm volatile("cp.async.wait_group 0;" ::: "memory")

__device__ __forceinline__ float hsig(float v) {
    return fminf(fmaxf(0.2f*v + 0.5f, 0.0f), 1.0f);
}

// ===========================================================================
// Aux kernels
// ===========================================================================
__global__ void init_kernel(const float* __restrict__ x) {
    for (int i = blockIdx.x*blockDim.x + threadIdx.x; i < ASZ; i += gridDim.x*blockDim.x) {
        int ch = i % 24;
        int p  = (i / 24) % HWc;
        int b  = i / (24*HWc);
        __half v = __float2half_rn(0.0f);
        if (ch >= 21)
            v = __float2half_rn(x[(((size_t)(b*Tc)*HWc) + p)*3 + (ch - 21)]);
        g_A0[i] = v;
    }
    for (int i = blockIdx.x*blockDim.x + threadIdx.x; i < CSZP; i += gridDim.x*blockDim.x)
        g_c[i] = 0.0f;
}

__global__ void xsplit_kernel(const float* __restrict__ x) {
    for (int i = blockIdx.x*blockDim.x + threadIdx.x; i < XSZ; i += gridDim.x*blockDim.x) {
        int p  = i % HWc;
        int r  = i / HWc;
        int c  = r % 3;
        int bt = r / 3;
        g_x[i] = __float2half_rn(x[((size_t)bt*HWc + p)*3 + c]);
    }
}

// Pack weights: B[n][k], n = 4*co+g, k = dy*80 + dx*24 + cin
// cin: 0..20 = h (rkern), 21..23 = x (kern); k%80>=72 and k>=240 zero pad
__global__ void packB_kernel(const float* __restrict__ kern, const float* __restrict__ rkern) {
    int i = blockIdx.x*blockDim.x + threadIdx.x;
    const int TOT = 88*BROW;
    if (i >= TOT) return;
    int n    = i / BROW;
    int k    = i - n*BROW;
    int co = n >> 2, g = n & 3;
    float w = 0.0f;
    if (k < 240 && co < Fc) {
        int dy = k / 80, r2 = k - dy*80;
        if (r2 < 72) {
            int dx = r2 / 24, cin = r2 - dx*24;
            int col = g*Fc + co;
            if (cin < 21) w = rkern[((dy*3 + dx)*Fc + cin     )*F4c + col];
            else          w = kern [((dy*3 + dx)*3  + (cin-21))*F4c + col];
        }
    }
    g_B[i] = __float2half_rn(w);
}

// ===========================================================================
// Persistent step kernel: 24 warps (m32n44), single-pass fp16 HMMA,
// cp.async double-buffered halo + c-state tiles
// ===========================================================================
__device__ __forceinline__ void prefetch_halo(
    uint32_t dstbase, int b, int x0, int y0,
    const __half* __restrict__ A, int tid) {
    const int TOTE = HROWS*HCOLS;     // 588 pixel-entries
    for (int i = tid; i < TOTE; i += NTHR) {
        int c = i % HCOLS;
        int r = i / HCOLS;
        int gy = y0 + r - 1, gx = x0 + c - 1;
        bool ok = ((unsigned)gy < (unsigned)Hc) && ((unsigned)gx < (unsigned)Wc);
        size_t off = ok ? ((size_t)b*HWc + (size_t)gy*Wc + gx)*24 : 0;
        const __half* src = A + off;
        uint32_t dst = dstbase + (uint32_t)(r*HCOLS + c)*48;
        uint32_t sz = ok ? 16u : 0u;
        #pragma unroll
        for (int q = 0; q < 3; q++)
            CP_ASYNC16(dst + q*16, src + q*8, sz);
    }
}

__device__ __forceinline__ void prefetch_c(
    uint32_t dstbase, int b, int ty, int x0, int tid) {
    // 21 co x 4 rows x 96 px f32 = 21*4*24 16B chunks (all in-bounds, padded)
    const int TOTC = Fc*TILE_H*24;    // 2016
    const float* cbase = g_c + ((size_t)(b*NTY + ty)*Fc)*TILE_H*CROWP + x0;
    for (int i = tid; i < TOTC; i += NTHR) {
        int ch16 = i % 24;
        int row  = (i / 24) & 3;
        int co   = i / 96;
        const float* src = cbase + (size_t)(co*TILE_H + row)*CROWP + ch16*4;
        uint32_t dst = dstbase + (uint32_t)((co*TILE_H + row)*TILE_W + ch16*4)*4;
        CP_ASYNC16(dst, src, 16u);
    }
}

__global__ __launch_bounds__(NTHR, 1)
void step_kernel(const float* __restrict__ bias, int t) {
    extern __shared__ unsigned char smem[];
    const uint32_t sbase = smem_to_u32(smem);
    const int tid  = threadIdx.x;
    const int w    = tid >> 5;
    const int lane = tid & 31;

    const __half* Ain = (t & 1) ? g_A1 : g_A0;
    __half*       Aout = (t & 1) ? g_A0 : g_A1;

    // ---- Stage B + bias once per CTA; zero overread pads ----
    {
        const float4* gB = reinterpret_cast<const float4*>(g_B);
        float4* sB = reinterpret_cast<float4*>(smem + SM_B);
        #pragma unroll 4
        for (int i = tid; i < B_TOTAL_B/16; i += NTHR) sB[i] = gB[i];
        if (tid < 88) {
            int co = tid >> 2, g = tid & 3;
            reinterpret_cast<float*>(smem + SM_BIAS)[tid] =
                (co < Fc) ? bias[g*Fc + co] : 0.0f;
        }
        // zero pad after HALO1 (halo1 overread target, never re-written)
        if (tid < 8)
            reinterpret_cast<uint32_t*>(smem + SM_HALO1 + HPLANE_B)[tid] = 0;
        // zero first 32B of HALO1 (halo0 overread target before first fill)
        if (tid >= 8 && tid < 16)
            reinterpret_cast<uint32_t*>(smem + SM_HALO1)[tid - 8] = 0;
    }

    // ---- Warp tiling: 24 warps = 4my x 3mx x 2nhalf, warp tile m32 x n44 ----
    const int nhalf = w & 1;
    const int mx    = (w >> 1) % 3;
    const int my    = w / 6;
    const int mxb   = mx * 32;
    const int NF    = nhalf ? 5 : 6;
    const uint32_t aLane  = (uint32_t)(lane & 15)*48 + (uint32_t)((lane >> 4) & 1)*16;
    const uint32_t bLane4 = (uint32_t)(lane & 7)*496 + (uint32_t)((lane >> 3) & 1)*16
                          + (uint32_t)((lane >> 4) & 1)*(8*496);
    const uint32_t bLane2 = (uint32_t)(lane & 7)*496 + (uint32_t)((lane >> 3) & 1)*16;
    const uint32_t nOff   = (uint32_t)nhalf * (48*496);
    const float* sb_all = reinterpret_cast<const float*>(smem + SM_BIAS);

    // ---- Prologue: prefetch first tile (halo + c) ----
    int idx = blockIdx.x;
    if (idx < NTILES) {
        int b0 = idx / (NTX*NTY), r0 = idx % (NTX*NTY);
        prefetch_halo(sbase + SM_HALO0, b0, (r0 & 1)*TILE_W, (r0 >> 1)*TILE_H,
                      Ain, tid);
        prefetch_c(sbase + SM_C0, b0, r0 >> 1, (r0 & 1)*TILE_W, tid);
    }
    CP_COMMIT();

    int cur = 0;
    for (; idx < NTILES; idx += GRID) {
        CP_WAIT0();
        __syncthreads();

        int nxt = idx + GRID;
        if (nxt < NTILES) {
            int bn = nxt / (NTX*NTY), rn = nxt % (NTX*NTY);
            prefetch_halo(sbase + (cur ? SM_HALO0 : SM_HALO1),
                          bn, (rn & 1)*TILE_W, (rn >> 1)*TILE_H, Ain, tid);
            prefetch_c(sbase + (cur ? SM_C0 : SM_C1),
                       bn, rn >> 1, (rn & 1)*TILE_W, tid);
        }
        CP_COMMIT();

        const int b  = idx / (NTX*NTY);
        const int rr = idx % (NTX*NTY);
        const int x0 = (rr & 1)*TILE_W;
        const int ty = rr >> 1;
        const int y0 = ty*TILE_H;
        const uint32_t Hbuf = sbase + (cur ? SM_HALO1 : SM_HALO0);
        float* Cs = reinterpret_cast<float*>(smem + (cur ? SM_C1 : SM_C0));

        // ---- Mainloop: single pass, f32 accum ----
        float d[2][6][4];
        #pragma unroll
        for (int mf = 0; mf < 2; mf++)
            #pragma unroll
            for (int nf = 0; nf < 6; nf++)
                #pragma unroll
                for (int q = 0; q < 4; q++) d[mf][nf][q] = 0.0f;

        {
            const uint32_t Bb = sbase + SM_B + nOff;
            #pragma unroll 1
            for (int dy = 0; dy < 3; dy++) {
                const uint32_t Arow = Hbuf + (uint32_t)((my + dy)*HCOLS + mxb)*48 + aLane;
                const uint32_t Brow = Bb + (uint32_t)dy*160;
                #pragma unroll
                for (int c = 0; c < 5; c++) {
                    uint32_t bq[12];
                    {
                        const uint32_t ba4 = Brow + bLane4 + c*32;
                        LDSM_X4(bq[0], bq[1], bq[2], bq[3], ba4);
                        LDSM_X4(bq[4], bq[5], bq[6], bq[7], ba4 + 2*(8*496));
                        if (nhalf) {
                            LDSM_X2(bq[8], bq[9], Brow + bLane2 + 4*(8*496) + c*32);
                        } else {
                            LDSM_X4(bq[8], bq[9], bq[10], bq[11], ba4 + 4*(8*496));
                        }
                    }
                    #pragma unroll
                    for (int mf = 0; mf < 2; mf++) {
                        uint32_t a0, a1, a2, a3;
                        LDSM_X4(a0, a1, a2, a3, Arow + mf*(16*48) + c*32);
                        #pragma unroll
                        for (int nf = 0; nf < 6; nf++)
                            if (nf < NF)
                                MMA_F32(d[mf][nf], a0, a1, a2, a3, bq[2*nf], bq[2*nf+1]);
                    }
                }
            }
        }

        // ---- Epilogue: gate update, c from smem, write h to Aout ----
        {
            const int gid    = lane >> 2;
            const int co_off = (lane >> 1) & 1;
            const bool lowrow = ((lane & 1) == 0);
            const int gy = y0 + my;
            const int cob = nhalf * 12;
            float* cg_tile = g_c + ((size_t)(b*NTY + ty)*Fc)*TILE_H*CROWP;
            #pragma unroll
            for (int mf = 0; mf < 2; mf++) {
                #pragma unroll
                for (int nf = 0; nf < 6; nf++) {
                    if (nf >= NF) continue;
                    float* dd = d[mf][nf];
                    float r0 = __shfl_xor_sync(0xFFFFFFFFu, dd[0], 1);
                    float r1 = __shfl_xor_sync(0xFFFFFFFFu, dd[1], 1);
                    float r2 = __shfl_xor_sync(0xFFFFFFFFu, dd[2], 1);
                    float r3 = __shfl_xor_sync(0xFFFFFFFFu, dd[3], 1);
                    float zi, zf, zg, zo;
                    int rowm;
                    if (lowrow) { zi = dd[0]; zf = dd[1]; zg = r0;    zo = r1;    rowm = gid; }
                    else        { zi = r2;    zf = r3;    zg = dd[2]; zo = dd[3]; rowm = gid + 8; }
                    const int co = cob + 2*nf + co_off;
                    const int lx = mxb + mf*16 + rowm;      // 0..95
                    const int gx = x0 + lx;
                    if (co < Fc && gx < Wc && gy < Hc) {
                        const float* sb = sb_all + co*4;
                        float ig = hsig(zi + sb[0]);
                        float fg = hsig(zf + sb[1]);
                        float gg = tanhf(zg + sb[2]);
                        float og = hsig(zo + sb[3]);
                        float cold = Cs[(co*TILE_H + my)*TILE_W + lx];
                        float cn = fg * cold + ig * gg;
                        cg_tile[(size_t)(co*TILE_H + my)*CROWP + gx] = cn;
                        float h = og * tanhf(cn);
                        size_t pix = (size_t)gy*Wc + gx;
                        Aout[((size_t)b*HWc + pix)*24 + co] = __float2half_rn(h);
                    }
                }
            }
            // x-forwarding: nhalf==1 warps write x(t+1) into slots 21..23
            if (nhalf) {
                const int t1 = t + 1;
                const int gy2 = y0 + my;
                for (int j = lane; j < 32*3; j += 32) {
                    int pxl = j / 3, ch = j - 3*pxl;
                    int gx = x0 + mxb + pxl;
                    if (gx < Wc && gy2 < Hc) {
                        size_t pix = (size_t)gy2*Wc + gx;
                        __half v = __float2half_rn(0.0f);
                        if (t1 < Tc)
                            v = g_x[((size_t)((b*Tc + t1)*3 + ch))*HWc + pix];
                        Aout[((size_t)b*HWc + pix)*24 + 21 + ch] = v;
                    }
                }
            }
        }
        cur ^= 1;
    }
}

// ===========================================================================
// out[b,h,w,co] = A0[b][pix][co] * mask[pix]
// ===========================================================================
__global__ void mask_out_kernel(const float* __restrict__ mask, float* __restrict__ out) {
    const int n = Bc*HWc*Fc;
    int i = blockIdx.x*blockDim.x + threadIdx.x;
    if (i >= n) return;
    int co   = i % Fc;
    int rest = i / Fc;
    int p    = rest % HWc;
    int b    = rest / HWc;
    out[i] = __half2float(g_A0[((size_t)b*HWc + p)*24 + co]) * mask[p];
}

// ===========================================================================
extern "C" void kernel_launch(void* const* d_in, const int* in_sizes, int n_in,
                              void* d_out, int out_size) {
    const float* x     = (const float*)d_in[0];
    const float* kern  = (const float*)d_in[1];
    const float* rkern = (const float*)d_in[2];
    const float* bias  = (const float*)d_in[3];
    const float* mask  = (const float*)d_in[4];
    float* out = (float*)d_out;
    (void)in_sizes; (void)n_in; (void)out_size;

    cudaFuncSetAttribute(step_kernel, cudaFuncAttributeMaxDynamicSharedMemorySize,
                         SMEM_BYTES);

    init_kernel<<<2048, 256>>>(x);
    xsplit_kernel<<<4096, 256>>>(x);
    packB_kernel<<<(88*BROW + 255)/256, 256>>>(kern, rkern);

    for (int t = 0; t < Tc; t++) {
        step_kernel<<<GRID, NTHR, SMEM_BYTES>>>(bias, t);
    }

    const int n = Bc*HWc*Fc;
    mask_out_kernel<<<(n + 255)/256, 256>>>(mask, out);
}